// round 1
// baseline (speedup 1.0000x reference)
#include <cuda_runtime.h>
#include <cuda_bf16.h>
#include <math.h>
#include <stdint.h>

// ---------------------------------------------------------------------------
// AutomaticBrightnessAndContrast
//   in : image f32 [3, H, W]   (single input)
//   out: f32 [3, H, W]
//
// Pipeline (5 launches, all graph-capturable, no allocations):
//   K0 zero scratch (device globals persist across graph replays!)
//   K1 fused: global max + histogram-under-scale-255 (one full read)
//   K2 conditional: histogram-under-scale-1, early-exits if max<=1.0
//   K3 tiny: cumsum + thresholds -> alpha_eff/beta_eff/hi/identity flag
//   K4 pointwise affine+clamp (read + write)
// ---------------------------------------------------------------------------

#define NUM_BINS 256
#define HIST_BLOCKS 1024
#define HIST_THREADS 256
#define WARPS_PER_BLOCK (HIST_THREADS / 32)

__device__ unsigned g_hist255[NUM_BINS];
__device__ unsigned g_hist1[NUM_BINS];
__device__ unsigned g_maxbits;          // order-encoded float max
__device__ float    g_alpha_eff;
__device__ float    g_beta_eff;
__device__ float    g_hi;
__device__ int      g_identity;         // 1 => pass input through unchanged

// monotone order-preserving float->uint encoding (works for negatives too)
__device__ __forceinline__ unsigned fkey(float f) {
    unsigned b = __float_as_uint(f);
    return (b & 0x80000000u) ? ~b : (b | 0x80000000u);
}
__device__ __forceinline__ float fkey_decode(unsigned k) {
    unsigned b = (k & 0x80000000u) ? (k & 0x7FFFFFFFu) : ~k;
    return __uint_as_float(b);
}

// ------------------------------- K0 ----------------------------------------
__global__ void zero_scratch_kernel() {
    int t = threadIdx.x;
    if (t < NUM_BINS) { g_hist255[t] = 0u; g_hist1[t] = 0u; }
    if (t == 0) g_maxbits = 0u;   // encodes the most-negative value
}

// ------------------------------- K1 ----------------------------------------
// One full read of the image. Computes:
//   - global max over every element
//   - 256-bin histogram of grayscale(image * 255)   [the "normalized" branch]
__global__ __launch_bounds__(HIST_THREADS)
void hist255_max_kernel(const float4* __restrict__ img, int n4per) {
    __shared__ unsigned sh[WARPS_PER_BLOCK][NUM_BINS];
    __shared__ float    smax[WARPS_PER_BLOCK];

    const int tid  = threadIdx.x;
    const int wid  = tid >> 5;
    const int lane = tid & 31;

    for (int i = tid; i < WARPS_PER_BLOCK * NUM_BINS; i += blockDim.x)
        (&sh[0][0])[i] = 0u;
    __syncthreads();

    const float bw = 255.0f / 256.0f;
    float lmax = -INFINITY;

    const int stride = gridDim.x * blockDim.x;
    for (int i = blockIdx.x * blockDim.x + tid; i < n4per; i += stride) {
        float4 r4 = img[i];
        float4 g4 = img[i + n4per];
        float4 b4 = img[i + 2 * n4per];

        lmax = fmaxf(lmax, fmaxf(fmaxf(fmaxf(r4.x, r4.y), fmaxf(r4.z, r4.w)),
                       fmaxf(fmaxf(fmaxf(g4.x, g4.y), fmaxf(g4.z, g4.w)),
                             fmaxf(fmaxf(b4.x, b4.y), fmaxf(b4.z, b4.w)))));

        const float* rp = (const float*)&r4;
        const float* gp = (const float*)&g4;
        const float* bp = (const float*)&b4;
        #pragma unroll
        for (int k = 0; k < 4; k++) {
            float rs = rp[k] * 255.0f;
            float gs = gp[k] * 255.0f;
            float bs = bp[k] * 255.0f;
            float gray = 0.299f * rs + 0.587f * gs + 0.114f * bs;
            if (gray >= 0.0f && gray <= 255.0f) {
                int idx = (int)floorf(gray / bw);
                idx = min(max(idx, 0), NUM_BINS - 1);
                atomicAdd(&sh[wid][idx], 1u);
            }
        }
    }
    __syncthreads();

    // flush per-warp histograms to global
    for (int b = tid; b < NUM_BINS; b += blockDim.x) {
        unsigned s = 0;
        #pragma unroll
        for (int w = 0; w < WARPS_PER_BLOCK; w++) s += sh[w][b];
        if (s) atomicAdd(&g_hist255[b], s);
    }

    // block max -> global
    #pragma unroll
    for (int off = 16; off; off >>= 1)
        lmax = fmaxf(lmax, __shfl_xor_sync(0xFFFFFFFFu, lmax, off));
    if (lane == 0) smax[wid] = lmax;
    __syncthreads();
    if (tid == 0) {
        float m = smax[0];
        #pragma unroll
        for (int w = 1; w < WARPS_PER_BLOCK; w++) m = fmaxf(m, smax[w]);
        atomicMax(&g_maxbits, fkey(m));
    }
}

// ------------------------------- K2 ----------------------------------------
// Runs only when NOT normalized (max > 1.0): histogram of grayscale(image).
// For the normalized case every block exits immediately (a few us).
__global__ __launch_bounds__(HIST_THREADS)
void hist1_kernel(const float4* __restrict__ img, int n4per) {
    if (fkey_decode(g_maxbits) <= 1.0f) return;

    __shared__ unsigned sh[WARPS_PER_BLOCK][NUM_BINS];
    const int tid = threadIdx.x;
    const int wid = tid >> 5;

    for (int i = tid; i < WARPS_PER_BLOCK * NUM_BINS; i += blockDim.x)
        (&sh[0][0])[i] = 0u;
    __syncthreads();

    const float bw = 255.0f / 256.0f;
    const int stride = gridDim.x * blockDim.x;
    for (int i = blockIdx.x * blockDim.x + tid; i < n4per; i += stride) {
        float4 r4 = img[i];
        float4 g4 = img[i + n4per];
        float4 b4 = img[i + 2 * n4per];
        const float* rp = (const float*)&r4;
        const float* gp = (const float*)&g4;
        const float* bp = (const float*)&b4;
        #pragma unroll
        for (int k = 0; k < 4; k++) {
            float gray = 0.299f * rp[k] + 0.587f * gp[k] + 0.114f * bp[k];
            if (gray >= 0.0f && gray <= 255.0f) {
                int idx = (int)floorf(gray / bw);
                idx = min(max(idx, 0), NUM_BINS - 1);
                atomicAdd(&sh[wid][idx], 1u);
            }
        }
    }
    __syncthreads();

    for (int b = tid; b < NUM_BINS; b += blockDim.x) {
        unsigned s = 0;
        #pragma unroll
        for (int w = 0; w < WARPS_PER_BLOCK; w++) s += sh[w][b];
        if (s) atomicAdd(&g_hist1[b], s);
    }
}

// ------------------------------- K3 ----------------------------------------
__global__ void params_kernel() {
    if (threadIdx.x != 0) return;

    float maxv = fkey_decode(g_maxbits);
    bool  is_norm = (maxv <= 1.0f);
    float scale = is_norm ? 255.0f : 1.0f;
    const unsigned* h = is_norm ? g_hist255 : g_hist1;

    float acc[NUM_BINS];
    float run = 0.0f;
    for (int i = 0; i < NUM_BINS; i++) { run += (float)h[i]; acc[i] = run; }
    float maximum = acc[NUM_BINS - 1];
    float clip = 1.0f * (maximum / 100.0f) / 2.0f;   // CLIP_HIST_PERCENT = 1.0

    int min_gray = 0, max_gray = 0;
    float upper = maximum - clip;
    for (int i = 0; i < NUM_BINS; i++) {
        min_gray += (acc[i] < clip)  ? 1 : 0;
        max_gray += (acc[i] < upper) ? 1 : 0;
    }
    max_gray -= 1;

    float span  = fmaxf((float)(max_gray - min_gray), 1.0f);
    float alpha = 255.0f / span;
    float beta  = -(float)min_gray * alpha;

    g_alpha_eff = alpha / scale;
    g_beta_eff  = beta  / scale;
    g_hi        = is_norm ? 1.0f : 255.0f;
    g_identity  = (max_gray > min_gray) ? 0 : 1;
}

// ------------------------------- K4 ----------------------------------------
__global__ __launch_bounds__(256)
void apply_kernel(const float4* __restrict__ in, float4* __restrict__ out, int n4) {
    int i = blockIdx.x * blockDim.x + threadIdx.x;
    if (i >= n4) return;
    float4 v = in[i];
    if (!g_identity) {
        float a  = g_alpha_eff;
        float b  = g_beta_eff;
        float hi = g_hi;
        v.x = fminf(fmaxf(v.x * a + b, 0.0f), hi);
        v.y = fminf(fmaxf(v.y * a + b, 0.0f), hi);
        v.z = fminf(fmaxf(v.z * a + b, 0.0f), hi);
        v.w = fminf(fmaxf(v.w * a + b, 0.0f), hi);
    }
    out[i] = v;
}

// ---------------------------------------------------------------------------
extern "C" void kernel_launch(void* const* d_in, const int* in_sizes, int n_in,
                              void* d_out, int out_size) {
    const float* img = (const float*)d_in[0];
    int n_total = in_sizes[0];          // 3 * H * W
    int n_per   = n_total / 3;          // H * W  (divisible by 4)
    int n4per   = n_per / 4;
    int n4      = n_total / 4;

    zero_scratch_kernel<<<1, 256>>>();
    hist255_max_kernel<<<HIST_BLOCKS, HIST_THREADS>>>((const float4*)img, n4per);
    hist1_kernel<<<HIST_BLOCKS, HIST_THREADS>>>((const float4*)img, n4per);
    params_kernel<<<1, 32>>>();
    apply_kernel<<<(n4 + 255) / 256, 256>>>((const float4*)img, (float4*)d_out, n4);
}

// round 2
// speedup vs baseline: 1.0580x; 1.0580x over previous
#include <cuda_runtime.h>
#include <cuda_bf16.h>
#include <math.h>
#include <stdint.h>

// ---------------------------------------------------------------------------
// AutomaticBrightnessAndContrast
//   in : image f32 [3, H, W]
//   out: f32 [3, H, W]
//
// Pipeline (4 launches):
//   K1 fused: global max + histogram-under-scale-255 (one full read)
//   K2 conditional: histogram-under-scale-1, early-exits if max<=1.0
//   K3 parallel: cumsum + thresholds -> params; ALSO resets scratch for the
//      next replay (globals are zero-init at load; K3 restores that state,
//      so no separate zeroing kernel is needed and behavior is deterministic)
//   K4 pointwise affine+clamp (read + write)
// ---------------------------------------------------------------------------

#define NUM_BINS 256
#define HIST_BLOCKS 1024
#define HIST_THREADS 256
#define WARPS_PER_BLOCK (HIST_THREADS / 32)

__device__ unsigned g_hist255[NUM_BINS];   // zero-init at module load
__device__ unsigned g_hist1[NUM_BINS];     // zero-init at module load
__device__ unsigned g_maxbits;             // zero-init (= most-negative key)
__device__ float    g_alpha_eff;
__device__ float    g_beta_eff;
__device__ float    g_hi;
__device__ int      g_identity;

// monotone order-preserving float->uint encoding
__device__ __forceinline__ unsigned fkey(float f) {
    unsigned b = __float_as_uint(f);
    return (b & 0x80000000u) ? ~b : (b | 0x80000000u);
}
__device__ __forceinline__ float fkey_decode(unsigned k) {
    unsigned b = (k & 0x80000000u) ? (k & 0x7FFFFFFFu) : ~k;
    return __uint_as_float(b);
}

// ------------------------------- K1 ----------------------------------------
__global__ __launch_bounds__(HIST_THREADS)
void hist255_max_kernel(const float4* __restrict__ img, int n4per) {
    __shared__ unsigned sh[WARPS_PER_BLOCK][NUM_BINS];
    __shared__ float    smax[WARPS_PER_BLOCK];

    const int tid  = threadIdx.x;
    const int wid  = tid >> 5;
    const int lane = tid & 31;

    for (int i = tid; i < WARPS_PER_BLOCK * NUM_BINS; i += blockDim.x)
        (&sh[0][0])[i] = 0u;
    __syncthreads();

    const float bw = 255.0f / 256.0f;
    float lmax = -INFINITY;

    const int stride = gridDim.x * blockDim.x;
    for (int i = blockIdx.x * blockDim.x + tid; i < n4per; i += stride) {
        float4 r4 = img[i];
        float4 g4 = img[i + n4per];
        float4 b4 = img[i + 2 * n4per];

        lmax = fmaxf(lmax, fmaxf(fmaxf(fmaxf(r4.x, r4.y), fmaxf(r4.z, r4.w)),
                       fmaxf(fmaxf(fmaxf(g4.x, g4.y), fmaxf(g4.z, g4.w)),
                             fmaxf(fmaxf(b4.x, b4.y), fmaxf(b4.z, b4.w)))));

        const float* rp = (const float*)&r4;
        const float* gp = (const float*)&g4;
        const float* bp = (const float*)&b4;
        #pragma unroll
        for (int k = 0; k < 4; k++) {
            float rs = rp[k] * 255.0f;
            float gs = gp[k] * 255.0f;
            float bs = bp[k] * 255.0f;
            float gray = 0.299f * rs + 0.587f * gs + 0.114f * bs;
            if (gray >= 0.0f && gray <= 255.0f) {
                int idx = (int)floorf(gray / bw);
                idx = min(max(idx, 0), NUM_BINS - 1);
                atomicAdd(&sh[wid][idx], 1u);
            }
        }
    }
    __syncthreads();

    for (int b = tid; b < NUM_BINS; b += blockDim.x) {
        unsigned s = 0;
        #pragma unroll
        for (int w = 0; w < WARPS_PER_BLOCK; w++) s += sh[w][b];
        if (s) atomicAdd(&g_hist255[b], s);
    }

    #pragma unroll
    for (int off = 16; off; off >>= 1)
        lmax = fmaxf(lmax, __shfl_xor_sync(0xFFFFFFFFu, lmax, off));
    if (lane == 0) smax[wid] = lmax;
    __syncthreads();
    if (tid == 0) {
        float m = smax[0];
        #pragma unroll
        for (int w = 1; w < WARPS_PER_BLOCK; w++) m = fmaxf(m, smax[w]);
        atomicMax(&g_maxbits, fkey(m));
    }
}

// ------------------------------- K2 ----------------------------------------
__global__ __launch_bounds__(HIST_THREADS)
void hist1_kernel(const float4* __restrict__ img, int n4per) {
    if (fkey_decode(g_maxbits) <= 1.0f) return;

    __shared__ unsigned sh[WARPS_PER_BLOCK][NUM_BINS];
    const int tid = threadIdx.x;
    const int wid = tid >> 5;

    for (int i = tid; i < WARPS_PER_BLOCK * NUM_BINS; i += blockDim.x)
        (&sh[0][0])[i] = 0u;
    __syncthreads();

    const float bw = 255.0f / 256.0f;
    const int stride = gridDim.x * blockDim.x;
    for (int i = blockIdx.x * blockDim.x + tid; i < n4per; i += stride) {
        float4 r4 = img[i];
        float4 g4 = img[i + n4per];
        float4 b4 = img[i + 2 * n4per];
        const float* rp = (const float*)&r4;
        const float* gp = (const float*)&g4;
        const float* bp = (const float*)&b4;
        #pragma unroll
        for (int k = 0; k < 4; k++) {
            float gray = 0.299f * rp[k] + 0.587f * gp[k] + 0.114f * bp[k];
            if (gray >= 0.0f && gray <= 255.0f) {
                int idx = (int)floorf(gray / bw);
                idx = min(max(idx, 0), NUM_BINS - 1);
                atomicAdd(&sh[wid][idx], 1u);
            }
        }
    }
    __syncthreads();

    for (int b = tid; b < NUM_BINS; b += blockDim.x) {
        unsigned s = 0;
        #pragma unroll
        for (int w = 0; w < WARPS_PER_BLOCK; w++) s += sh[w][b];
        if (s) atomicAdd(&g_hist1[b], s);
    }
}

// ------------------------------- K3 ----------------------------------------
// 256 threads: parallel inclusive scan of the selected histogram (exact in
// fp32 — counts are integers, total = 2^24), threshold counts via
// __syncthreads_count, then reset all scratch for the next graph replay.
__global__ __launch_bounds__(NUM_BINS)
void params_kernel() {
    __shared__ float acc[NUM_BINS];
    __shared__ float sbuf[NUM_BINS];

    const int tid = threadIdx.x;

    float maxv = fkey_decode(g_maxbits);
    bool  is_norm = (maxv <= 1.0f);
    float scale = is_norm ? 255.0f : 1.0f;

    float v = (float)(is_norm ? g_hist255[tid] : g_hist1[tid]);

    // Hillis-Steele inclusive scan over 256 elements
    acc[tid] = v;
    __syncthreads();
    #pragma unroll
    for (int off = 1; off < NUM_BINS; off <<= 1) {
        float add = (tid >= off) ? acc[tid - off] : 0.0f;
        __syncthreads();
        acc[tid] += add;
        __syncthreads();
    }

    float maximum = acc[NUM_BINS - 1];
    float clip = (maximum / 100.0f) / 2.0f;          // CLIP_HIST_PERCENT = 1.0
    float upper = maximum - clip;

    int min_gray = __syncthreads_count(acc[tid] < clip);
    int max_gray = __syncthreads_count(acc[tid] < upper) - 1;

    if (tid == 0) {
        float span  = fmaxf((float)(max_gray - min_gray), 1.0f);
        float alpha = 255.0f / span;
        float beta  = -(float)min_gray * alpha;
        g_alpha_eff = alpha / scale;
        g_beta_eff  = beta  / scale;
        g_hi        = is_norm ? 1.0f : 255.0f;
        g_identity  = (max_gray > min_gray) ? 0 : 1;
        g_maxbits   = 0u;
    }
    // restore zero-state so next replay starts clean (deterministic)
    g_hist255[tid] = 0u;
    g_hist1[tid]   = 0u;
    (void)sbuf;
}

// ------------------------------- K4 ----------------------------------------
__global__ __launch_bounds__(256)
void apply_kernel(const float4* __restrict__ in, float4* __restrict__ out, int n4) {
    int i = blockIdx.x * blockDim.x + threadIdx.x;
    if (i >= n4) return;
    float4 v = in[i];
    if (!g_identity) {
        float a  = g_alpha_eff;
        float b  = g_beta_eff;
        float hi = g_hi;
        v.x = fminf(fmaxf(v.x * a + b, 0.0f), hi);
        v.y = fminf(fmaxf(v.y * a + b, 0.0f), hi);
        v.z = fminf(fmaxf(v.z * a + b, 0.0f), hi);
        v.w = fminf(fmaxf(v.w * a + b, 0.0f), hi);
    }
    out[i] = v;
}

// ---------------------------------------------------------------------------
extern "C" void kernel_launch(void* const* d_in, const int* in_sizes, int n_in,
                              void* d_out, int out_size) {
    const float* img = (const float*)d_in[0];
    int n_total = in_sizes[0];
    int n_per   = n_total / 3;
    int n4per   = n_per / 4;
    int n4      = n_total / 4;

    hist255_max_kernel<<<HIST_BLOCKS, HIST_THREADS>>>((const float4*)img, n4per);
    hist1_kernel<<<HIST_BLOCKS, HIST_THREADS>>>((const float4*)img, n4per);
    params_kernel<<<1, NUM_BINS>>>();
    apply_kernel<<<(n4 + 255) / 256, 256>>>((const float4*)img, (float4*)d_out, n4);
}

// round 4
// speedup vs baseline: 1.0962x; 1.0361x over previous
#include <cuda_runtime.h>
#include <cuda_bf16.h>
#include <math.h>
#include <stdint.h>

// ---------------------------------------------------------------------------
// AutomaticBrightnessAndContrast  —  in/out f32 [3, H, W]
// K1 fused max + hist(scale=255)   (one full read)
// K2 conditional hist(scale=1)     (early-exits when max<=1)
// K3 parallel scan -> params; resets scratch for next graph replay
// K4 pointwise affine+clamp        (read + write), 2x float4/thread, streaming
// ---------------------------------------------------------------------------

#define NUM_BINS 256
#define HIST_BLOCKS 1024
#define HIST_THREADS 256
#define WARPS_PER_BLOCK (HIST_THREADS / 32)

__device__ unsigned g_hist255[NUM_BINS];   // zero-init at module load
__device__ unsigned g_hist1[NUM_BINS];     // zero-init at module load
__device__ unsigned g_maxbits;             // zero-init (= most-negative key)
__device__ float    g_alpha_eff;
__device__ float    g_beta_eff;
__device__ float    g_hi;
__device__ int      g_identity;

__device__ __forceinline__ unsigned fkey(float f) {
    unsigned b = __float_as_uint(f);
    return (b & 0x80000000u) ? ~b : (b | 0x80000000u);
}
__device__ __forceinline__ float fkey_decode(unsigned k) {
    unsigned b = (k & 0x80000000u) ? (k & 0x7FFFFFFFu) : ~k;
    return __uint_as_float(b);
}

// inv bin width: 1 / (255/256) = 256/255
#define INV_BW (256.0f / 255.0f)

__device__ __forceinline__ void hist_px255(unsigned* h, float r, float g, float b) {
    // gray255 = 255*(0.299 r + 0.587 g + 0.114 b), coefficients pre-folded
    float gray = fmaf(r, 76.245f, fmaf(g, 149.685f, b * 29.07f));
    if (gray >= 0.0f && gray <= 255.0f) {
        int idx = (int)(gray * INV_BW);       // gray>=0 -> trunc == floor
        idx = min(idx, NUM_BINS - 1);
        atomicAdd(&h[idx], 1u);
    }
}
__device__ __forceinline__ void hist_px1(unsigned* h, float r, float g, float b) {
    float gray = fmaf(r, 0.299f, fmaf(g, 0.587f, b * 0.114f));
    if (gray >= 0.0f && gray <= 255.0f) {
        int idx = (int)(gray * INV_BW);
        idx = min(idx, NUM_BINS - 1);
        atomicAdd(&h[idx], 1u);
    }
}

// ------------------------------- K1 ----------------------------------------
__global__ __launch_bounds__(HIST_THREADS)
void hist255_max_kernel(const float4* __restrict__ img, int n4per) {
    __shared__ unsigned sh[WARPS_PER_BLOCK][NUM_BINS];
    __shared__ float    smax[WARPS_PER_BLOCK];

    const int tid  = threadIdx.x;
    const int wid  = tid >> 5;
    const int lane = tid & 31;

    for (int i = tid; i < WARPS_PER_BLOCK * NUM_BINS; i += blockDim.x)
        (&sh[0][0])[i] = 0u;
    __syncthreads();

    unsigned* myh = sh[wid];
    float lmax = -INFINITY;

    const int stride  = gridDim.x * blockDim.x;
    const int stride2 = 2 * stride;
    int i = blockIdx.x * blockDim.x + tid;

    for (; i + stride < n4per; i += stride2) {
        // batch of 2: issue all 6 128-bit loads up front (MLP=6)
        float4 r4a = img[i];
        float4 g4a = img[i + n4per];
        float4 b4a = img[i + 2 * n4per];
        float4 r4b = img[i + stride];
        float4 g4b = img[i + stride + n4per];
        float4 b4b = img[i + stride + 2 * n4per];

        lmax = fmaxf(lmax, fmaxf(fmaxf(fmaxf(r4a.x, r4a.y), fmaxf(r4a.z, r4a.w)),
                       fmaxf(fmaxf(fmaxf(g4a.x, g4a.y), fmaxf(g4a.z, g4a.w)),
                             fmaxf(fmaxf(fmaxf(b4a.x, b4a.y), fmaxf(b4a.z, b4a.w)),
                       fmaxf(fmaxf(fmaxf(r4b.x, r4b.y), fmaxf(r4b.z, r4b.w)),
                       fmaxf(fmaxf(fmaxf(g4b.x, g4b.y), fmaxf(g4b.z, g4b.w)),
                             fmaxf(fmaxf(b4b.x, b4b.y), fmaxf(b4b.z, b4b.w))))))));

        hist_px255(myh, r4a.x, g4a.x, b4a.x);
        hist_px255(myh, r4a.y, g4a.y, b4a.y);
        hist_px255(myh, r4a.z, g4a.z, b4a.z);
        hist_px255(myh, r4a.w, g4a.w, b4a.w);
        hist_px255(myh, r4b.x, g4b.x, b4b.x);
        hist_px255(myh, r4b.y, g4b.y, b4b.y);
        hist_px255(myh, r4b.z, g4b.z, b4b.z);
        hist_px255(myh, r4b.w, g4b.w, b4b.w);
    }
    for (; i < n4per; i += stride) {
        float4 r4 = img[i];
        float4 g4 = img[i + n4per];
        float4 b4 = img[i + 2 * n4per];
        lmax = fmaxf(lmax, fmaxf(fmaxf(fmaxf(r4.x, r4.y), fmaxf(r4.z, r4.w)),
                       fmaxf(fmaxf(fmaxf(g4.x, g4.y), fmaxf(g4.z, g4.w)),
                             fmaxf(fmaxf(b4.x, b4.y), fmaxf(b4.z, b4.w)))));
        hist_px255(myh, r4.x, g4.x, b4.x);
        hist_px255(myh, r4.y, g4.y, b4.y);
        hist_px255(myh, r4.z, g4.z, b4.z);
        hist_px255(myh, r4.w, g4.w, b4.w);
    }
    __syncthreads();

    for (int b = tid; b < NUM_BINS; b += blockDim.x) {
        unsigned s = 0;
        #pragma unroll
        for (int w = 0; w < WARPS_PER_BLOCK; w++) s += sh[w][b];
        if (s) atomicAdd(&g_hist255[b], s);
    }

    #pragma unroll
    for (int off = 16; off; off >>= 1)
        lmax = fmaxf(lmax, __shfl_xor_sync(0xFFFFFFFFu, lmax, off));
    if (lane == 0) smax[wid] = lmax;
    __syncthreads();
    if (tid == 0) {
        float m = smax[0];
        #pragma unroll
        for (int w = 1; w < WARPS_PER_BLOCK; w++) m = fmaxf(m, smax[w]);
        atomicMax(&g_maxbits, fkey(m));
    }
}

// ------------------------------- K2 ----------------------------------------
__global__ __launch_bounds__(HIST_THREADS)
void hist1_kernel(const float4* __restrict__ img, int n4per) {
    if (fkey_decode(g_maxbits) <= 1.0f) return;

    __shared__ unsigned sh[WARPS_PER_BLOCK][NUM_BINS];
    const int tid = threadIdx.x;
    const int wid = tid >> 5;

    for (int i = tid; i < WARPS_PER_BLOCK * NUM_BINS; i += blockDim.x)
        (&sh[0][0])[i] = 0u;
    __syncthreads();

    unsigned* myh = sh[wid];
    const int stride = gridDim.x * blockDim.x;
    for (int i = blockIdx.x * blockDim.x + tid; i < n4per; i += stride) {
        float4 r4 = img[i];
        float4 g4 = img[i + n4per];
        float4 b4 = img[i + 2 * n4per];
        hist_px1(myh, r4.x, g4.x, b4.x);
        hist_px1(myh, r4.y, g4.y, b4.y);
        hist_px1(myh, r4.z, g4.z, b4.z);
        hist_px1(myh, r4.w, g4.w, b4.w);
    }
    __syncthreads();

    for (int b = tid; b < NUM_BINS; b += blockDim.x) {
        unsigned s = 0;
        #pragma unroll
        for (int w = 0; w < WARPS_PER_BLOCK; w++) s += sh[w][b];
        if (s) atomicAdd(&g_hist1[b], s);
    }
}

// ------------------------------- K3 ----------------------------------------
__global__ __launch_bounds__(NUM_BINS)
void params_kernel() {
    __shared__ float acc[NUM_BINS];
    const int tid = threadIdx.x;

    float maxv = fkey_decode(g_maxbits);
    bool  is_norm = (maxv <= 1.0f);
    float scale = is_norm ? 255.0f : 1.0f;

    float v = (float)(is_norm ? g_hist255[tid] : g_hist1[tid]);

    acc[tid] = v;
    __syncthreads();
    #pragma unroll
    for (int off = 1; off < NUM_BINS; off <<= 1) {
        float add = (tid >= off) ? acc[tid - off] : 0.0f;
        __syncthreads();
        acc[tid] += add;
        __syncthreads();
    }

    float maximum = acc[NUM_BINS - 1];
    float clip = (maximum / 100.0f) / 2.0f;          // CLIP_HIST_PERCENT = 1.0
    float upper = maximum - clip;

    int min_gray = __syncthreads_count(acc[tid] < clip);
    int max_gray = __syncthreads_count(acc[tid] < upper) - 1;

    if (tid == 0) {
        float span  = fmaxf((float)(max_gray - min_gray), 1.0f);
        float alpha = 255.0f / span;
        float beta  = -(float)min_gray * alpha;
        g_alpha_eff = alpha / scale;
        g_beta_eff  = beta  / scale;
        g_hi        = is_norm ? 1.0f : 255.0f;
        g_identity  = (max_gray > min_gray) ? 0 : 1;
        g_maxbits   = 0u;
    }
    g_hist255[tid] = 0u;
    g_hist1[tid]   = 0u;
}

// ------------------------------- K4 ----------------------------------------
// 2 float4 per thread, loads issued before compute, streaming ld/st.
__global__ __launch_bounds__(256)
void apply_kernel(const float4* __restrict__ in, float4* __restrict__ out, int n4) {
    int base = blockIdx.x * 512 + threadIdx.x;
    int i0 = base;
    int i1 = base + 256;

    float4 v0, v1;
    bool ok0 = i0 < n4, ok1 = i1 < n4;
    if (ok0) v0 = __ldcs(&in[i0]);
    if (ok1) v1 = __ldcs(&in[i1]);

    int   ident = g_identity;
    float a  = g_alpha_eff;
    float b  = g_beta_eff;
    float hi = g_hi;

    if (!ident) {
        v0.x = fminf(fmaxf(fmaf(v0.x, a, b), 0.0f), hi);
        v0.y = fminf(fmaxf(fmaf(v0.y, a, b), 0.0f), hi);
        v0.z = fminf(fmaxf(fmaf(v0.z, a, b), 0.0f), hi);
        v0.w = fminf(fmaxf(fmaf(v0.w, a, b), 0.0f), hi);
        v1.x = fminf(fmaxf(fmaf(v1.x, a, b), 0.0f), hi);
        v1.y = fminf(fmaxf(fmaf(v1.y, a, b), 0.0f), hi);
        v1.z = fminf(fmaxf(fmaf(v1.z, a, b), 0.0f), hi);
        v1.w = fminf(fmaxf(fmaf(v1.w, a, b), 0.0f), hi);
    }
    if (ok0) __stcs(&out[i0], v0);
    if (ok1) __stcs(&out[i1], v1);
}

// ---------------------------------------------------------------------------
extern "C" void kernel_launch(void* const* d_in, const int* in_sizes, int n_in,
                              void* d_out, int out_size) {
    const float* img = (const float*)d_in[0];
    int n_total = in_sizes[0];
    int n_per   = n_total / 3;
    int n4per   = n_per / 4;
    int n4      = n_total / 4;

    hist255_max_kernel<<<HIST_BLOCKS, HIST_THREADS>>>((const float4*)img, n4per);
    hist1_kernel<<<HIST_BLOCKS, HIST_THREADS>>>((const float4*)img, n4per);
    params_kernel<<<1, NUM_BINS>>>();
    int apply_blocks = (n4 + 511) / 512;
    apply_kernel<<<apply_blocks, 256>>>((const float4*)img, (float4*)d_out, n4);
}